// round 1
// baseline (speedup 1.0000x reference)
#include <cuda_runtime.h>
#include <math.h>

#define T_LEN  80
#define BATCH  2048
#define EMB    100
#define EPAD   112          // EMB padded to multiple of BK
#define UNITS  1024
#define NGATE  4096         // 4 * UNITS

#define BM 64
#define BN 64               // per-gate N tile (real tile is 4x this across gates)
#define BK 16

// ---- scratch (static __device__ arrays; no runtime allocation) ----
__device__ float g_X[(size_t)T_LEN * BATCH * EPAD];   // gathered, padded embeddings
__device__ float g_W0p[(size_t)EPAD * NGATE];         // zero-padded W0
__device__ float g_h0[2][(size_t)BATCH * UNITS];
__device__ float g_c0[(size_t)BATCH * UNITS];
__device__ float g_h1[2][(size_t)BATCH * UNITS];
__device__ float g_c1[(size_t)BATCH * UNITS];

__device__ __forceinline__ float sigf(float x) { return 1.f / (1.f + expf(-x)); }

// ---------------------------------------------------------------------------
__global__ void zero_kernel(float* __restrict__ p, int n) {
    int i = blockIdx.x * blockDim.x + threadIdx.x;
    int stride = gridDim.x * blockDim.x;
    for (; i < n; i += stride) p[i] = 0.f;
}

__global__ void pad_w0_kernel(const float* __restrict__ W0) {
    int i = blockIdx.x * blockDim.x + threadIdx.x;
    if (i >= EPAD * NGATE) return;
    int k = i / NGATE;
    g_W0p[i] = (k < EMB) ? W0[i] : 0.f;   // same row stride (4096) for k < EMB
}

// one block per (t, b); gather emb row with zero pad to EPAD
__global__ void gather_kernel(const int* __restrict__ inputs,
                              const float* __restrict__ emb) {
    int blk = blockIdx.x;                 // t * BATCH + b
    int t = blk / BATCH;
    int b = blk - t * BATCH;
    int e = threadIdx.x;                  // 128 threads
    if (e >= EPAD) return;
    int idx = inputs[b * T_LEN + t];
    float v = (e < EMB) ? emb[(size_t)idx * EMB + e] : 0.f;
    g_X[(size_t)blk * EPAD + e] = v;
}

// ---------------------------------------------------------------------------
// Fused LSTM step: z = A1@B1 + A2@B2 + bias  (B matrices are [K, 4096],
// 4 gate column blocks of UNITS each), then gate nonlinearity + cell update
// in the epilogue. Each thread owns a 4x4 (b, j) subtile for ALL 4 gates.
__global__ __launch_bounds__(256, 2)
void lstm_step_kernel(const float* __restrict__ A1, int lda1, int K1,
                      const float* __restrict__ B1,
                      const float* __restrict__ A2,   // h_prev [BATCH, UNITS]
                      const float* __restrict__ B2,   // U      [UNITS, 4096]
                      const float* __restrict__ bias, // [4096]
                      float* __restrict__ c_state,    // in/out [BATCH, UNITS]
                      float* __restrict__ h_out) {    // [BATCH, UNITS]
    __shared__ __align__(16) float As[BK][BM];
    __shared__ __align__(16) float Bs[4][BK][BN];

    const int tid = threadIdx.x;
    const int tx = tid & 15;      // N-dim lane (4 cols each)
    const int ty = tid >> 4;      // M-dim lane (4 rows each)
    const int m0 = blockIdx.y * BM;
    const int j0 = blockIdx.x * BN;

    float acc[4][4][4];
    #pragma unroll
    for (int g = 0; g < 4; ++g) {
        #pragma unroll
        for (int jj = 0; jj < 4; ++jj) {
            float bv = bias[g * UNITS + j0 + tx * 4 + jj];
            #pragma unroll
            for (int ii = 0; ii < 4; ++ii) acc[g][ii][jj] = bv;
        }
    }

    // load mappings
    const int am  = tid >> 2;          // 0..63  (A row within tile)
    const int akq = (tid & 3) * 4;     // 0,4,8,12 (A k chunk)
    const int bk  = tid >> 4;          // 0..15  (B row within k-tile)
    const int bc  = (tid & 15) * 4;    // B col chunk

    #pragma unroll 1
    for (int pass = 0; pass < 2; ++pass) {
        const float* A = pass ? A2 : A1;
        const float* B = pass ? B2 : B1;
        const int lda  = pass ? UNITS : lda1;
        const int K    = pass ? UNITS : K1;

        #pragma unroll 1
        for (int k0 = 0; k0 < K; k0 += BK) {
            __syncthreads();
            float4 av = *(const float4*)&A[(size_t)(m0 + am) * lda + k0 + akq];
            As[akq + 0][am] = av.x;
            As[akq + 1][am] = av.y;
            As[akq + 2][am] = av.z;
            As[akq + 3][am] = av.w;
            #pragma unroll
            for (int g = 0; g < 4; ++g) {
                float4 bv = *(const float4*)
                    &B[(size_t)(k0 + bk) * NGATE + g * UNITS + j0 + bc];
                *(float4*)&Bs[g][bk][bc] = bv;
            }
            __syncthreads();

            #pragma unroll
            for (int kk = 0; kk < BK; ++kk) {
                float4 af = *(const float4*)&As[kk][ty * 4];
                float a[4] = {af.x, af.y, af.z, af.w};
                #pragma unroll
                for (int g = 0; g < 4; ++g) {
                    float4 bf = *(const float4*)&Bs[g][kk][tx * 4];
                    float bb[4] = {bf.x, bf.y, bf.z, bf.w};
                    #pragma unroll
                    for (int ii = 0; ii < 4; ++ii)
                        #pragma unroll
                        for (int jj = 0; jj < 4; ++jj)
                            acc[g][ii][jj] += a[ii] * bb[jj];
                }
            }
        }
    }

    // fused LSTM gate epilogue (Keras order: i, f, g, o)
    #pragma unroll
    for (int ii = 0; ii < 4; ++ii) {
        int b = m0 + ty * 4 + ii;
        #pragma unroll
        for (int jj = 0; jj < 4; ++jj) {
            int col = j0 + tx * 4 + jj;
            size_t off = (size_t)b * UNITS + col;
            float iv = sigf(acc[0][ii][jj]);
            float fv = sigf(acc[1][ii][jj]);
            float gv = tanhf(acc[2][ii][jj]);
            float ov = sigf(acc[3][ii][jj]);
            float cn = fv * c_state[off] + iv * gv;
            c_state[off] = cn;
            h_out[off] = ov * tanhf(cn);
        }
    }
}

// ---------------------------------------------------------------------------
__global__ void fc_kernel(const float* __restrict__ h1,
                          const float* __restrict__ fcW,
                          const float* __restrict__ fcb,
                          float* __restrict__ out) {
    int b = blockIdx.x;               // BATCH blocks
    int lane = threadIdx.x;           // 128 threads
    float s = 0.f;
    for (int k = lane; k < UNITS; k += 128)
        s += h1[(size_t)b * UNITS + k] * fcW[k];
    __shared__ float red[128];
    red[lane] = s;
    __syncthreads();
    for (int off = 64; off > 0; off >>= 1) {
        if (lane < off) red[lane] += red[lane + off];
        __syncthreads();
    }
    if (lane == 0) out[b] = sigf(red[0] + fcb[0]);
}

// ---------------------------------------------------------------------------
extern "C" void kernel_launch(void* const* d_in, const int* in_sizes, int n_in,
                              void* d_out, int out_size) {
    const int*   inputs = (const int*)  d_in[0];
    const float* emb    = (const float*)d_in[1];
    const float* W0     = (const float*)d_in[2];
    const float* U0     = (const float*)d_in[3];
    const float* b0     = (const float*)d_in[4];
    const float* W1     = (const float*)d_in[5];
    const float* U1     = (const float*)d_in[6];
    const float* b1     = (const float*)d_in[7];
    const float* fcW    = (const float*)d_in[8];
    const float* fcb    = (const float*)d_in[9];
    float* out = (float*)d_out;

    float *pX, *pW0p, *ph0, *pc0, *ph1, *pc1;
    cudaGetSymbolAddress((void**)&pX,   g_X);
    cudaGetSymbolAddress((void**)&pW0p, g_W0p);
    cudaGetSymbolAddress((void**)&ph0,  g_h0);
    cudaGetSymbolAddress((void**)&pc0,  g_c0);
    cudaGetSymbolAddress((void**)&ph1,  g_h1);
    cudaGetSymbolAddress((void**)&pc1,  g_c1);

    float* h0buf[2] = {ph0, ph0 + (size_t)BATCH * UNITS};
    float* h1buf[2] = {ph1, ph1 + (size_t)BATCH * UNITS};

    const int NBU = BATCH * UNITS;
    zero_kernel<<<1024, 256>>>(h0buf[0], NBU);
    zero_kernel<<<1024, 256>>>(pc0, NBU);
    zero_kernel<<<1024, 256>>>(h1buf[0], NBU);
    zero_kernel<<<1024, 256>>>(pc1, NBU);
    pad_w0_kernel<<<(EPAD * NGATE + 255) / 256, 256>>>(W0);
    gather_kernel<<<T_LEN * BATCH, 128>>>(inputs, emb);

    dim3 grid(UNITS / BN, BATCH / BM);   // (16, 32)
    int p = 0;
    for (int t = 0; t < T_LEN; ++t) {
        // layer 0: z = x_t @ W0pad + h0 @ U0 + b0
        lstm_step_kernel<<<grid, 256>>>(pX + (size_t)t * BATCH * EPAD, EPAD, EPAD,
                                        pW0p, h0buf[p], U0, b0,
                                        pc0, h0buf[p ^ 1]);
        // layer 1: z = h0_new @ W1 + h1 @ U1 + b1
        lstm_step_kernel<<<grid, 256>>>(h0buf[p ^ 1], UNITS, UNITS,
                                        W1, h1buf[p], U1, b1,
                                        pc1, h1buf[p ^ 1]);
        p ^= 1;
    }

    fc_kernel<<<BATCH, 128>>>(h1buf[p], fcW, fcb, out);
}

// round 3
// speedup vs baseline: 3.3827x; 3.3827x over previous
#include <cuda_runtime.h>
#include <cuda_bf16.h>
#include <math.h>
#include <cstdint>

#define T_LEN  80
#define BATCH  2048
#define EMB    100
#define EPAD   128
#define UNITS  1024
#define NGATE  4096

#define BM   128     // batch rows per CTA
#define BNU  32      // units per CTA (output cols = 4 gates * 32 = 128)
#define BN   128
#define BK   32      // k per pipeline stage
#define SSTR 40      // smem row stride in bf16 (conflict-free)

// ---- persistent scratch ----
__device__ __nv_bfloat16 g_X[(size_t)T_LEN*BATCH*EPAD];
__device__ __nv_bfloat16 g_W0t[(size_t)NGATE*EPAD];     // [4096][128]  K-major (transposed)
__device__ __nv_bfloat16 g_U0t[(size_t)NGATE*UNITS];    // [4096][1024]
__device__ __nv_bfloat16 g_W1t[(size_t)NGATE*UNITS];
__device__ __nv_bfloat16 g_U1t[(size_t)NGATE*UNITS];
__device__ __nv_bfloat16 g_h0[2][(size_t)BATCH*UNITS];
__device__ __nv_bfloat16 g_h1[2][(size_t)BATCH*UNITS];
__device__ float g_c0[(size_t)UNITS*BATCH];             // transposed [unit][batch]
__device__ float g_c1[(size_t)UNITS*BATCH];

__device__ __forceinline__ uint32_t smem_u32(const void* p) {
    uint32_t a;
    asm("{ .reg .u64 t; cvta.to.shared.u64 t, %1; cvt.u32.u64 %0, t; }" : "=r"(a) : "l"(p));
    return a;
}
__device__ __forceinline__ void cpasync16(uint32_t dst, const void* src) {
    asm volatile("cp.async.cg.shared.global [%0], [%1], 16;" :: "r"(dst), "l"(src));
}
#define CP_COMMIT() asm volatile("cp.async.commit_group;" ::: "memory")
#define CP_WAIT(n)  asm volatile("cp.async.wait_group %0;" :: "n"(n) : "memory")

__device__ __forceinline__ void mma16816(float* d, const uint32_t* a, const uint32_t* b) {
    asm volatile("mma.sync.aligned.m16n8k16.row.col.f32.bf16.bf16.f32 "
        "{%0,%1,%2,%3}, {%4,%5,%6,%7}, {%8,%9}, {%0,%1,%2,%3};"
        : "+f"(d[0]), "+f"(d[1]), "+f"(d[2]), "+f"(d[3])
        : "r"(a[0]), "r"(a[1]), "r"(a[2]), "r"(a[3]), "r"(b[0]), "r"(b[1]));
}

__device__ __forceinline__ float sigf(float x) { return 1.f / (1.f + expf(-x)); }

// ---------------------------------------------------------------------------
__global__ void zero_f32(float* __restrict__ p, int n) {
    int i = blockIdx.x * blockDim.x + threadIdx.x;
    for (; i < n; i += gridDim.x * blockDim.x) p[i] = 0.f;
}

// transpose fp32 [K][4096] -> bf16 [4096][Kpad], zero-padding K..Kpad
__global__ void transpose_bf16(const float* __restrict__ in, int K, int Kpad,
                               __nv_bfloat16* __restrict__ out) {
    __shared__ float tile[32][33];
    int n0 = blockIdx.x * 32, k0 = blockIdx.y * 32;
    int tx = threadIdx.x, ty = threadIdx.y;   // 32 x 8
    for (int i = ty; i < 32; i += 8) {
        int k = k0 + i;
        tile[i][tx] = (k < K) ? in[(size_t)k * NGATE + n0 + tx] : 0.f;
    }
    __syncthreads();
    for (int i = ty; i < 32; i += 8) {
        int n = n0 + i, kk = k0 + tx;
        if (kk < Kpad) out[(size_t)n * Kpad + kk] = __float2bfloat16(tile[tx][i]);
    }
}

__global__ void gather_x(const int* __restrict__ inputs, const float* __restrict__ emb) {
    int blk = blockIdx.x;                 // t*BATCH + b
    int t = blk / BATCH, b = blk - t * BATCH;
    int e = threadIdx.x;                  // 128
    int idx = inputs[b * T_LEN + t];
    float v = (e < EMB) ? emb[(size_t)idx * EMB + e] : 0.f;
    g_X[(size_t)blk * EPAD + e] = __float2bfloat16(v);
}

// ---------------------------------------------------------------------------
// Fused LSTM step via HMMA mma.sync: z[128,128] = A1@B1^T + A2@B2^T (+bias),
// bf16 inputs, fp32 accum in registers; LSTM gate epilogue fused per thread.
// N-tiles (n8) interleave gates: tile tn -> gate (tn&3), unit-block (tn>>2),
// so every thread owns all 4 gates of its (batch, unit) coordinates.
__global__ __launch_bounds__(256, 2)
void lstm_step(const __nv_bfloat16* __restrict__ A1, int K1,
               const __nv_bfloat16* __restrict__ B1,   // [4096][K1]
               const __nv_bfloat16* __restrict__ A2,   // h_prev [2048][1024]
               const __nv_bfloat16* __restrict__ B2,   // U^T    [4096][1024]
               const float* __restrict__ bias,         // [4096]
               float* __restrict__ c_t,                // [1024][2048] transposed
               __nv_bfloat16* __restrict__ h_out) {    // [2048][1024]
    __shared__ __align__(16) __nv_bfloat16 As[2][BM][SSTR];
    __shared__ __align__(16) __nv_bfloat16 Bs[2][BN][SSTR];

    const int tid  = threadIdx.x;
    const int lane = tid & 31, wid = tid >> 5;
    const int wm = wid >> 2, wn = wid & 3;       // warp 64x32 at (wm, wn)
    const int m0 = blockIdx.y * BM, j0 = blockIdx.x * BNU;

    const int S1 = K1 / BK;
    const int S  = S1 + UNITS / BK;

    // load mapping (per thread: 2 x 16B for A, 2 x 16B for B per stage)
    int rowA[2], kcA[2], rowB[2], nglB[2];
    #pragma unroll
    for (int i = 0; i < 2; ++i) {
        int cid = tid + i * 256;
        rowA[i] = cid & 127; kcA[i] = cid >> 7;
        int rr = cid & 127;
        int tn = rr >> 3, win = rr & 7;
        rowB[i] = rr;
        nglB[i] = (tn & 3) * UNITS + j0 + (tn >> 2) * 8 + win;
    }

    auto load_stage = [&](int s, int buf) {
        const __nv_bfloat16* A; const __nv_bfloat16* B; int lda, k0;
        if (s < S1) { A = A1; B = B1; lda = K1;   k0 = s * BK; }
        else        { A = A2; B = B2; lda = UNITS; k0 = (s - S1) * BK; }
        #pragma unroll
        for (int i = 0; i < 2; ++i) {
            cpasync16(smem_u32(&As[buf][rowA[i]][kcA[i] * 8]),
                      A + (size_t)(m0 + rowA[i]) * lda + k0 + kcA[i] * 8);
            cpasync16(smem_u32(&Bs[buf][rowB[i]][kcA[i] * 8]),
                      B + (size_t)nglB[i] * lda + k0 + kcA[i] * 8);
        }
    };

    float acc[4][4][4];
    #pragma unroll
    for (int mt = 0; mt < 4; ++mt)
        #pragma unroll
        for (int g = 0; g < 4; ++g)
            #pragma unroll
            for (int v = 0; v < 4; ++v) acc[mt][g][v] = 0.f;

    const int ar = wm * 64 + (lane >> 2);
    const int ac = (lane & 3) * 2;

    load_stage(0, 0);
    CP_COMMIT();

    #pragma unroll 1
    for (int s = 0; s < S; ++s) {
        if (s + 1 < S) { load_stage(s + 1, (s + 1) & 1); CP_COMMIT(); CP_WAIT(1); }
        else CP_WAIT(0);
        __syncthreads();
        const int buf = s & 1;
        #pragma unroll
        for (int kk = 0; kk < BK; kk += 16) {
            uint32_t a[4][4];
            #pragma unroll
            for (int mt = 0; mt < 4; ++mt) {
                const __nv_bfloat16* p = &As[buf][ar + mt * 16][kk + ac];
                a[mt][0] = *(const uint32_t*)p;
                a[mt][1] = *(const uint32_t*)(p + 8 * SSTR);
                a[mt][2] = *(const uint32_t*)(p + 8);
                a[mt][3] = *(const uint32_t*)(p + 8 * SSTR + 8);
            }
            #pragma unroll
            for (int g = 0; g < 4; ++g) {
                const __nv_bfloat16* q = &Bs[buf][(wn * 4 + g) * 8 + (lane >> 2)][kk + ac];
                uint32_t b[2] = { *(const uint32_t*)q, *(const uint32_t*)(q + 8) };
                #pragma unroll
                for (int mt = 0; mt < 4; ++mt) mma16816(acc[mt][g], a[mt], b);
            }
        }
        __syncthreads();
    }

    // ---- fused LSTM gate epilogue (Keras order: i, f, g, o) ----
    const int jc = wn * 8 + (lane & 3) * 2;      // unit col base within CTA
    float bia[4][2];
    #pragma unroll
    for (int g = 0; g < 4; ++g) {
        bia[g][0] = bias[g * UNITS + j0 + jc];
        bia[g][1] = bias[g * UNITS + j0 + jc + 1];
    }
    #pragma unroll
    for (int mt = 0; mt < 4; ++mt) {
        #pragma unroll
        for (int p = 0; p < 2; ++p) {
            const int brow = m0 + wm * 64 + mt * 16 + (lane >> 2) + p * 8;
            __nv_bfloat162 hv;
            #pragma unroll
            for (int q = 0; q < 2; ++q) {
                float zi = acc[mt][0][p * 2 + q] + bia[0][q];
                float zf = acc[mt][1][p * 2 + q] + bia[1][q];
                float zg = acc[mt][2][p * 2 + q] + bia[2][q];
                float zo = acc[mt][3][p * 2 + q] + bia[3][q];
                size_t coff = (size_t)(j0 + jc + q) * BATCH + brow;
                float cn = sigf(zf) * c_t[coff] + sigf(zi) * tanhf(zg);
                c_t[coff] = cn;
                ((__nv_bfloat16*)&hv)[q] = __float2bfloat16(sigf(zo) * tanhf(cn));
            }
            *(__nv_bfloat162*)(h_out + (size_t)brow * UNITS + j0 + jc) = hv;
        }
    }
}

// ---------------------------------------------------------------------------
__global__ void fc_kernel(const __nv_bfloat16* __restrict__ h1,
                          const float* __restrict__ fcW,
                          const float* __restrict__ fcb,
                          float* __restrict__ out) {
    int b = blockIdx.x;
    int lane = threadIdx.x;            // 32
    float s = 0.f;
    for (int k = lane; k < UNITS; k += 32)
        s += __bfloat162float(h1[(size_t)b * UNITS + k]) * fcW[k];
    #pragma unroll
    for (int off = 16; off > 0; off >>= 1)
        s += __shfl_xor_sync(0xFFFFFFFFu, s, off);
    if (lane == 0) out[b] = sigf(s + fcb[0]);
}

// ---------------------------------------------------------------------------
extern "C" void kernel_launch(void* const* d_in, const int* in_sizes, int n_in,
                              void* d_out, int out_size) {
    const int*   inputs = (const int*)  d_in[0];
    const float* emb    = (const float*)d_in[1];
    const float* W0     = (const float*)d_in[2];
    const float* U0     = (const float*)d_in[3];
    const float* b0     = (const float*)d_in[4];
    const float* W1     = (const float*)d_in[5];
    const float* U1     = (const float*)d_in[6];
    const float* b1     = (const float*)d_in[7];
    const float* fcW    = (const float*)d_in[8];
    const float* fcb    = (const float*)d_in[9];
    float* out = (float*)d_out;

    __nv_bfloat16 *pX, *pW0t, *pU0t, *pW1t, *pU1t, *ph0, *ph1;
    float *pc0, *pc1;
    cudaGetSymbolAddress((void**)&pX,   g_X);
    cudaGetSymbolAddress((void**)&pW0t, g_W0t);
    cudaGetSymbolAddress((void**)&pU0t, g_U0t);
    cudaGetSymbolAddress((void**)&pW1t, g_W1t);
    cudaGetSymbolAddress((void**)&pU1t, g_U1t);
    cudaGetSymbolAddress((void**)&ph0,  g_h0);
    cudaGetSymbolAddress((void**)&ph1,  g_h1);
    cudaGetSymbolAddress((void**)&pc0,  g_c0);
    cudaGetSymbolAddress((void**)&pc1,  g_c1);

    __nv_bfloat16* h0buf[2] = {ph0, ph0 + (size_t)BATCH * UNITS};
    __nv_bfloat16* h1buf[2] = {ph1, ph1 + (size_t)BATCH * UNITS};

    const int NBU = BATCH * UNITS;
    zero_f32<<<512, 256>>>((float*)h0buf[0], NBU / 2);   // bf16 pair per float
    zero_f32<<<512, 256>>>((float*)h1buf[0], NBU / 2);
    zero_f32<<<512, 256>>>(pc0, NBU);
    zero_f32<<<512, 256>>>(pc1, NBU);

    dim3 tb(32, 8);
    transpose_bf16<<<dim3(NGATE / 32, EPAD / 32),  tb>>>(W0, EMB,   EPAD,  pW0t);
    transpose_bf16<<<dim3(NGATE / 32, UNITS / 32), tb>>>(U0, UNITS, UNITS, pU0t);
    transpose_bf16<<<dim3(NGATE / 32, UNITS / 32), tb>>>(W1, UNITS, UNITS, pW1t);
    transpose_bf16<<<dim3(NGATE / 32, UNITS / 32), tb>>>(U1, UNITS, UNITS, pU1t);
    gather_x<<<T_LEN * BATCH, 128>>>(inputs, emb);

    dim3 grid(UNITS / BNU, BATCH / BM);   // (32, 16)
    int p = 0;
    for (int t = 0; t < T_LEN; ++t) {
        lstm_step<<<grid, 256>>>(pX + (size_t)t * BATCH * EPAD, EPAD,
                                 pW0t, h0buf[p], pU0t, b0, pc0, h0buf[p ^ 1]);
        lstm_step<<<grid, 256>>>(h0buf[p ^ 1], UNITS,
                                 pW1t, h1buf[p], pU1t, b1, pc1, h1buf[p ^ 1]);
        p ^= 1;
    }
    fc_kernel<<<BATCH, 32>>>(h1buf[p], fcW, fcb, out);
}

// round 4
// speedup vs baseline: 3.6227x; 1.0709x over previous
#include <cuda_runtime.h>
#include <cuda_bf16.h>
#include <math.h>
#include <cstdint>

#define T_LEN  80
#define BATCH  2048
#define EMB    100
#define EPAD   128
#define UNITS  1024
#define NGATE  4096

#define BM   128     // batch rows per CTA
#define BNU  32      // units per CTA (output cols = 4 gates * 32 = 128)
#define BN   128
#define BK   32      // k per pipeline stage
#define NSTG 3       // cp.async pipeline depth
#define SSTR 40      // smem row stride in bf16 (conflict-free)

#define SMEM_STAGE  (2 * BM * SSTR)              // bf16 elems per stage (A+B)
#define SMEM_ELEMS  (NSTG * SMEM_STAGE)
#define SMEM_BYTES  (SMEM_ELEMS * 2)

// ---- persistent scratch ----
__device__ __nv_bfloat16 g_X[(size_t)T_LEN*BATCH*EPAD];
__device__ __nv_bfloat16 g_W0t[(size_t)NGATE*EPAD];     // [4096][128]  K-major (transposed)
__device__ __nv_bfloat16 g_U0t[(size_t)NGATE*UNITS];    // [4096][1024]
__device__ __nv_bfloat16 g_W1t[(size_t)NGATE*UNITS];
__device__ __nv_bfloat16 g_U1t[(size_t)NGATE*UNITS];
__device__ __nv_bfloat16 g_h0[2][(size_t)BATCH*UNITS];
__device__ __nv_bfloat16 g_h1[2][(size_t)BATCH*UNITS];
__device__ float g_c0[(size_t)UNITS*BATCH];             // transposed [unit][batch]
__device__ float g_c1[(size_t)UNITS*BATCH];

__device__ __forceinline__ uint32_t smem_u32(const void* p) {
    uint32_t a;
    asm("{ .reg .u64 t; cvta.to.shared.u64 t, %1; cvt.u32.u64 %0, t; }" : "=r"(a) : "l"(p));
    return a;
}
__device__ __forceinline__ void cpasync16(uint32_t dst, const void* src) {
    asm volatile("cp.async.cg.shared.global [%0], [%1], 16;" :: "r"(dst), "l"(src));
}
#define CP_COMMIT() asm volatile("cp.async.commit_group;" ::: "memory")
#define CP_WAIT(n)  asm volatile("cp.async.wait_group %0;" :: "n"(n) : "memory")

__device__ __forceinline__ void mma16816(float* d, const uint32_t* a, const uint32_t* b) {
    asm volatile("mma.sync.aligned.m16n8k16.row.col.f32.bf16.bf16.f32 "
        "{%0,%1,%2,%3}, {%4,%5,%6,%7}, {%8,%9}, {%0,%1,%2,%3};"
        : "+f"(d[0]), "+f"(d[1]), "+f"(d[2]), "+f"(d[3])
        : "r"(a[0]), "r"(a[1]), "r"(a[2]), "r"(a[3]), "r"(b[0]), "r"(b[1]));
}

__device__ __forceinline__ float sigf(float x) { return 1.f / (1.f + expf(-x)); }

// ---------------------------------------------------------------------------
__global__ void zero_f32(float* __restrict__ p, int n) {
    int i = blockIdx.x * blockDim.x + threadIdx.x;
    for (; i < n; i += gridDim.x * blockDim.x) p[i] = 0.f;
}

// transpose fp32 [K][4096] -> bf16 [4096][Kpad], zero-padding K..Kpad
__global__ void transpose_bf16(const float* __restrict__ in, int K, int Kpad,
                               __nv_bfloat16* __restrict__ out) {
    __shared__ float tile[32][33];
    int n0 = blockIdx.x * 32, k0 = blockIdx.y * 32;
    int tx = threadIdx.x, ty = threadIdx.y;   // 32 x 8
    for (int i = ty; i < 32; i += 8) {
        int k = k0 + i;
        tile[i][tx] = (k < K) ? in[(size_t)k * NGATE + n0 + tx] : 0.f;
    }
    __syncthreads();
    for (int i = ty; i < 32; i += 8) {
        int n = n0 + i, kk = k0 + tx;
        if (kk < Kpad) out[(size_t)n * Kpad + kk] = __float2bfloat16(tile[tx][i]);
    }
}

__global__ void gather_x(const int* __restrict__ inputs, const float* __restrict__ emb) {
    int blk = blockIdx.x;                 // t*BATCH + b
    int t = blk / BATCH, b = blk - t * BATCH;
    int e = threadIdx.x;                  // 128
    int idx = inputs[b * T_LEN + t];
    float v = (e < EMB) ? emb[(size_t)idx * EMB + e] : 0.f;
    g_X[(size_t)blk * EPAD + e] = __float2bfloat16(v);
}

// ---------------------------------------------------------------------------
// Fused LSTM step via HMMA mma.sync: z[128,128] = A1@B1^T + A2@B2^T (+bias),
// bf16 in, fp32 accum; 4 warps, warp tile 64x64, 3-stage cp.async pipeline.
// N-tiles (n8) interleave gates: tile tn -> gate (tn&3), unit-block (tn>>2),
// so every thread owns all 4 gates of its (batch, unit) coordinates.
__global__ __launch_bounds__(128, 2)
void lstm_step(const __nv_bfloat16* __restrict__ A1, int K1,
               const __nv_bfloat16* __restrict__ B1,   // [4096][K1]
               const __nv_bfloat16* __restrict__ A2,   // h_prev [2048][1024]
               const __nv_bfloat16* __restrict__ B2,   // U^T    [4096][1024]
               const float* __restrict__ bias,         // [4096]
               float* __restrict__ c_t,                // [1024][2048] transposed
               __nv_bfloat16* __restrict__ h_out) {    // [2048][1024]
    extern __shared__ __align__(16) __nv_bfloat16 smem[];
    // stage layout: [stage][ A:128*SSTR | B:128*SSTR ]

    const int tid  = threadIdx.x;
    const int lane = tid & 31, wid = tid >> 5;
    const int wm = wid >> 1, wn = wid & 1;       // warp 64x64 at (wm, wn)
    const int m0 = blockIdx.y * BM, j0 = blockIdx.x * BNU;

    const int S1 = K1 / BK;
    const int S  = S1 + UNITS / BK;

    // load mapping: per stage each thread copies 4 x 16B for A and 4 x 16B
    // for B; lanes hit consecutive rows at a fixed 16B chunk (conflict-free).
    int rowA[4], chA[4], nglB[4];
    #pragma unroll
    for (int i = 0; i < 4; ++i) {
        int cid = tid + i * 128;
        rowA[i] = cid & 127; chA[i] = cid >> 7;
        int rr = cid & 127;
        int tn = rr >> 3, win = rr & 7;
        nglB[i] = (tn & 3) * UNITS + j0 + (tn >> 2) * 8 + win;
    }

    auto load_stage = [&](int s, int buf) {
        const __nv_bfloat16* A; const __nv_bfloat16* B; int lda, k0;
        if (s < S1) { A = A1; B = B1; lda = K1;    k0 = s * BK; }
        else        { A = A2; B = B2; lda = UNITS; k0 = (s - S1) * BK; }
        __nv_bfloat16* As = smem + buf * SMEM_STAGE;
        __nv_bfloat16* Bs = As + BM * SSTR;
        #pragma unroll
        for (int i = 0; i < 4; ++i) {
            cpasync16(smem_u32(&As[rowA[i] * SSTR + chA[i] * 8]),
                      A + (size_t)(m0 + rowA[i]) * lda + k0 + chA[i] * 8);
            cpasync16(smem_u32(&Bs[rowA[i] * SSTR + chA[i] * 8]),
                      B + (size_t)nglB[i] * lda + k0 + chA[i] * 8);
        }
    };

    // accumulators initialized with bias (per-column, replicated over rows)
    const int jcbase = (lane & 3) * 2;           // col pair base within n8
    float acc[4][8][4];
    #pragma unroll
    for (int j = 0; j < 8; ++j) {
        int g = j & 3;
        int junit = j0 + (wn * 2 + (j >> 2)) * 8 + jcbase;
        float b0 = bias[g * UNITS + junit];
        float b1 = bias[g * UNITS + junit + 1];
        #pragma unroll
        for (int mt = 0; mt < 4; ++mt) {
            acc[mt][j][0] = b0; acc[mt][j][1] = b1;
            acc[mt][j][2] = b0; acc[mt][j][3] = b1;
        }
    }

    const int ar = wm * 64 + (lane >> 2);
    const int ac = (lane & 3) * 2;

    load_stage(0, 0); CP_COMMIT();
    load_stage(1, 1); CP_COMMIT();

    #pragma unroll 1
    for (int s = 0; s < S; ++s) {
        CP_WAIT(1);
        __syncthreads();
        if (s + 2 < S) load_stage(s + 2, (s + 2) % NSTG);
        CP_COMMIT();                              // uniform cadence (may be empty)

        const __nv_bfloat16* As = smem + (s % NSTG) * SMEM_STAGE;
        const __nv_bfloat16* Bs = As + BM * SSTR;
        #pragma unroll
        for (int kk = 0; kk < BK; kk += 16) {
            uint32_t a[4][4], b[8][2];
            #pragma unroll
            for (int mt = 0; mt < 4; ++mt) {
                const __nv_bfloat16* p = &As[(ar + mt * 16) * SSTR + kk + ac];
                a[mt][0] = *(const uint32_t*)p;
                a[mt][1] = *(const uint32_t*)(p + 8 * SSTR);
                a[mt][2] = *(const uint32_t*)(p + 8);
                a[mt][3] = *(const uint32_t*)(p + 8 * SSTR + 8);
            }
            #pragma unroll
            for (int j = 0; j < 8; ++j) {
                const __nv_bfloat16* q = &Bs[((wn * 8 + j) * 8 + (lane >> 2)) * SSTR + kk + ac];
                b[j][0] = *(const uint32_t*)q;
                b[j][1] = *(const uint32_t*)(q + 8);
            }
            #pragma unroll
            for (int mt = 0; mt < 4; ++mt)
                #pragma unroll
                for (int j = 0; j < 8; ++j)
                    mma16816(acc[mt][j], a[mt], b[j]);
        }
        __syncthreads();
    }

    // ---- fused LSTM gate epilogue (Keras order: i, f, g, o) ----
    #pragma unroll
    for (int ub = 0; ub < 2; ++ub) {
        const int jc = j0 + (wn * 2 + ub) * 8 + jcbase;
        #pragma unroll
        for (int mt = 0; mt < 4; ++mt) {
            #pragma unroll
            for (int p = 0; p < 2; ++p) {
                const int brow = m0 + wm * 64 + mt * 16 + (lane >> 2) + p * 8;
                __nv_bfloat162 hv;
                #pragma unroll
                for (int q = 0; q < 2; ++q) {
                    float zi = acc[mt][ub * 4 + 0][p * 2 + q];
                    float zf = acc[mt][ub * 4 + 1][p * 2 + q];
                    float zg = acc[mt][ub * 4 + 2][p * 2 + q];
                    float zo = acc[mt][ub * 4 + 3][p * 2 + q];
                    size_t coff = (size_t)(jc + q) * BATCH + brow;
                    float cn = sigf(zf) * c_t[coff] + sigf(zi) * tanhf(zg);
                    c_t[coff] = cn;
                    ((__nv_bfloat16*)&hv)[q] = __float2bfloat16(sigf(zo) * tanhf(cn));
                }
                *(__nv_bfloat162*)(h_out + (size_t)brow * UNITS + jc) = hv;
            }
        }
    }
}

// ---------------------------------------------------------------------------
__global__ void fc_kernel(const __nv_bfloat16* __restrict__ h1,
                          const float* __restrict__ fcW,
                          const float* __restrict__ fcb,
                          float* __restrict__ out) {
    int b = blockIdx.x;
    int lane = threadIdx.x;            // 32
    float s = 0.f;
    for (int k = lane; k < UNITS; k += 32)
        s += __bfloat162float(h1[(size_t)b * UNITS + k]) * fcW[k];
    #pragma unroll
    for (int off = 16; off > 0; off >>= 1)
        s += __shfl_xor_sync(0xFFFFFFFFu, s, off);
    if (lane == 0) out[b] = sigf(s + fcb[0]);
}

// ---------------------------------------------------------------------------
extern "C" void kernel_launch(void* const* d_in, const int* in_sizes, int n_in,
                              void* d_out, int out_size) {
    const int*   inputs = (const int*)  d_in[0];
    const float* emb    = (const float*)d_in[1];
    const float* W0     = (const float*)d_in[2];
    const float* U0     = (const float*)d_in[3];
    const float* b0     = (const float*)d_in[4];
    const float* W1     = (const float*)d_in[5];
    const float* U1     = (const float*)d_in[6];
    const float* b1     = (const float*)d_in[7];
    const float* fcW    = (const float*)d_in[8];
    const float* fcb    = (const float*)d_in[9];
    float* out = (float*)d_out;

    cudaFuncSetAttribute(lstm_step, cudaFuncAttributeMaxDynamicSharedMemorySize, SMEM_BYTES);

    __nv_bfloat16 *pX, *pW0t, *pU0t, *pW1t, *pU1t, *ph0, *ph1;
    float *pc0, *pc1;
    cudaGetSymbolAddress((void**)&pX,   g_X);
    cudaGetSymbolAddress((void**)&pW0t, g_W0t);
    cudaGetSymbolAddress((void**)&pU0t, g_U0t);
    cudaGetSymbolAddress((void**)&pW1t, g_W1t);
    cudaGetSymbolAddress((void**)&pU1t, g_U1t);
    cudaGetSymbolAddress((void**)&ph0,  g_h0);
    cudaGetSymbolAddress((void**)&ph1,  g_h1);
    cudaGetSymbolAddress((void**)&pc0,  g_c0);
    cudaGetSymbolAddress((void**)&pc1,  g_c1);

    __nv_bfloat16* h0buf[2] = {ph0, ph0 + (size_t)BATCH * UNITS};
    __nv_bfloat16* h1buf[2] = {ph1, ph1 + (size_t)BATCH * UNITS};

    const int NBU = BATCH * UNITS;
    zero_f32<<<512, 256>>>((float*)h0buf[0], NBU / 2);   // bf16 pair per float
    zero_f32<<<512, 256>>>((float*)h1buf[0], NBU / 2);
    zero_f32<<<512, 256>>>(pc0, NBU);
    zero_f32<<<512, 256>>>(pc1, NBU);

    dim3 tb(32, 8);
    transpose_bf16<<<dim3(NGATE / 32, EPAD / 32),  tb>>>(W0, EMB,   EPAD,  pW0t);
    transpose_bf16<<<dim3(NGATE / 32, UNITS / 32), tb>>>(U0, UNITS, UNITS, pU0t);
    transpose_bf16<<<dim3(NGATE / 32, UNITS / 32), tb>>>(W1, UNITS, UNITS, pW1t);
    transpose_bf16<<<dim3(NGATE / 32, UNITS / 32), tb>>>(U1, UNITS, UNITS, pU1t);
    gather_x<<<T_LEN * BATCH, 128>>>(inputs, emb);

    dim3 grid(UNITS / BNU, BATCH / BM);   // (32, 16)
    int p = 0;
    for (int t = 0; t < T_LEN; ++t) {
        lstm_step<<<grid, 128, SMEM_BYTES>>>(pX + (size_t)t * BATCH * EPAD, EPAD,
                                             pW0t, h0buf[p], pU0t, b0, pc0, h0buf[p ^ 1]);
        lstm_step<<<grid, 128, SMEM_BYTES>>>(h0buf[p ^ 1], UNITS,
                                             pW1t, h1buf[p], pU1t, b1, pc1, h1buf[p ^ 1]);
        p ^= 1;
    }
    fc_kernel<<<BATCH, 32>>>(h1buf[p], fcW, fcb, out);
}

// round 5
// speedup vs baseline: 3.8737x; 1.0693x over previous
#include <cuda_runtime.h>
#include <cuda_bf16.h>
#include <math.h>
#include <cstdint>

#define T_LEN  80
#define BATCH  2048
#define EMB    100
#define EPAD   128
#define UNITS  1024
#define NGATE  4096

#define BM   128     // batch rows per CTA
#define BNU  32      // units per CTA (output cols = 4 gates * 32 = 128)
#define BK   32      // k per pipeline stage
#define NSTG 4       // cp.async pipeline depth (ring)
#define SSTR 40      // smem row stride in bf16 (conflict-free)

#define SMEM_STAGE  (2 * BM * SSTR)              // bf16 elems per stage (A+B)
#define SMEM_BYTES  (NSTG * SMEM_STAGE * 2)      // 81920 B

// ---- persistent scratch ----
__device__ __nv_bfloat16 g_X[(size_t)T_LEN*BATCH*EPAD];
__device__ __nv_bfloat16 g_W0t[(size_t)NGATE*EPAD];     // [4096][128]  K-major (transposed)
__device__ __nv_bfloat16 g_U0t[(size_t)NGATE*UNITS];    // [4096][1024]
__device__ __nv_bfloat16 g_W1t[(size_t)NGATE*UNITS];
__device__ __nv_bfloat16 g_U1t[(size_t)NGATE*UNITS];
__device__ __nv_bfloat16 g_h0s[(size_t)(T_LEN+1)*BATCH*UNITS];  // h0 ring, slot t
__device__ __nv_bfloat16 g_h1[2][(size_t)BATCH*UNITS];
__device__ float g_c0[(size_t)UNITS*BATCH];             // transposed [unit][batch]
__device__ float g_c1[(size_t)UNITS*BATCH];

__device__ __forceinline__ uint32_t smem_u32(const void* p) {
    uint32_t a;
    asm("{ .reg .u64 t; cvta.to.shared.u64 t, %1; cvt.u32.u64 %0, t; }" : "=r"(a) : "l"(p));
    return a;
}
__device__ __forceinline__ void cpasync16(uint32_t dst, const void* src) {
    asm volatile("cp.async.cg.shared.global [%0], [%1], 16;" :: "r"(dst), "l"(src));
}
#define CP_COMMIT() asm volatile("cp.async.commit_group;" ::: "memory")
#define CP_WAIT(n)  asm volatile("cp.async.wait_group %0;" :: "n"(n) : "memory")

__device__ __forceinline__ void mma16816(float* d, const uint32_t* a, const uint32_t* b) {
    asm volatile("mma.sync.aligned.m16n8k16.row.col.f32.bf16.bf16.f32 "
        "{%0,%1,%2,%3}, {%4,%5,%6,%7}, {%8,%9}, {%0,%1,%2,%3};"
        : "+f"(d[0]), "+f"(d[1]), "+f"(d[2]), "+f"(d[3])
        : "r"(a[0]), "r"(a[1]), "r"(a[2]), "r"(a[3]), "r"(b[0]), "r"(b[1]));
}

__device__ __forceinline__ float sigf(float x) { return 1.f / (1.f + expf(-x)); }

// ---------------------------------------------------------------------------
// Prologue kernel 1: zero initial states
__global__ void init_zero() {
    uint32_t* h0 = (uint32_t*)g_h0s;            // slot 0
    uint32_t* h1 = (uint32_t*)g_h1[0];
    int stride = gridDim.x * blockDim.x;
    int i = blockIdx.x * blockDim.x + threadIdx.x;
    const int n16 = BATCH * UNITS / 2;
    for (int k = i; k < n16; k += stride) { h0[k] = 0u; h1[k] = 0u; }
    const int n32 = BATCH * UNITS;
    for (int k = i; k < n32; k += stride) { g_c0[k] = 0.f; g_c1[k] = 0.f; }
}

// Prologue kernel 2: transpose all 4 weight matrices fp32 [K][4096] ->
// bf16 [4096][Kpad] (zero-pad K..Kpad). blockIdx.z selects the matrix.
__global__ void transpose_all(const float* __restrict__ W0, const float* __restrict__ U0,
                              const float* __restrict__ W1, const float* __restrict__ U1) {
    __shared__ float tile[32][33];
    const float* in; __nv_bfloat16* out; int K, Kpad;
    switch (blockIdx.z) {
        case 0:  in = W0; out = g_W0t; K = EMB;   Kpad = EPAD;  break;
        case 1:  in = U0; out = g_U0t; K = UNITS; Kpad = UNITS; break;
        case 2:  in = W1; out = g_W1t; K = UNITS; Kpad = UNITS; break;
        default: in = U1; out = g_U1t; K = UNITS; Kpad = UNITS; break;
    }
    int n0 = blockIdx.x * 32, k0 = blockIdx.y * 32;
    if (k0 >= Kpad) return;
    int tx = threadIdx.x, ty = threadIdx.y;   // 32 x 8
    for (int i = ty; i < 32; i += 8) {
        int k = k0 + i;
        tile[i][tx] = (k < K) ? in[(size_t)k * NGATE + n0 + tx] : 0.f;
    }
    __syncthreads();
    for (int i = ty; i < 32; i += 8) {
        int n = n0 + i, kk = k0 + tx;
        out[(size_t)n * Kpad + kk] = __float2bfloat16(tile[tx][i]);
    }
}

// Prologue kernel 3: gather + pad embeddings, bf16
__global__ void gather_x(const int* __restrict__ inputs, const float* __restrict__ emb) {
    int blk = blockIdx.x;                 // t*BATCH + b
    int t = blk / BATCH, b = blk - t * BATCH;
    int e = threadIdx.x;                  // 128
    int idx = inputs[b * T_LEN + t];
    float v = (e < EMB) ? emb[(size_t)idx * EMB + e] : 0.f;
    g_X[(size_t)blk * EPAD + e] = __float2bfloat16(v);
}

// ---------------------------------------------------------------------------
// One "round": blockIdx.z==0 runs layer0 step r (if r < T_LEN),
//              blockIdx.z==1 runs layer1 step r-1 (if r >= 1).
// These are independent; the kernel boundary enforces the cross-round deps.
// GEMM: z[128,128] = A1@B1^T + A2@B2^T (+bias), bf16 HMMA, fp32 accum,
// 4 warps (64x64 warp tile), 4-stage cp.async ring, ONE barrier per stage.
// N-tiles interleave gates (tn -> gate tn&3, unit-block tn>>2) so each thread
// owns all 4 gates of its (batch, unit) coords -> LSTM epilogue in registers.
__global__ __launch_bounds__(128, 2)
void lstm_round(const float* __restrict__ b0, float* __restrict__ c0,
                const float* __restrict__ b1, float* __restrict__ c1,
                int r) {
    const __nv_bfloat16 *A1, *B1, *A2, *B2;
    const float* bias; float* c_t; __nv_bfloat16* h_out;
    int K1;
    if (blockIdx.z == 0) {
        if (r == T_LEN) return;
        A1 = g_X + (size_t)r * BATCH * EPAD;  K1 = EPAD;  B1 = g_W0t;
        A2 = g_h0s + (size_t)r * BATCH * UNITS;           B2 = g_U0t;
        bias = b0; c_t = c0;
        h_out = g_h0s + (size_t)(r + 1) * BATCH * UNITS;
    } else {
        if (r == 0) return;
        int t = r - 1;
        A1 = g_h0s + (size_t)(t + 1) * BATCH * UNITS;  K1 = UNITS;  B1 = g_W1t;
        A2 = g_h1[t & 1];                                            B2 = g_U1t;
        bias = b1; c_t = c1;
        h_out = g_h1[(t + 1) & 1];
    }

    extern __shared__ __align__(16) __nv_bfloat16 smem[];
    const int tid  = threadIdx.x;
    const int lane = tid & 31, wid = tid >> 5;
    const int wm = wid >> 1, wn = wid & 1;       // warp 64x64 at (wm, wn)
    const int m0 = blockIdx.y * BM, j0 = blockIdx.x * BNU;

    const int S1 = K1 / BK;
    const int S  = S1 + UNITS / BK;

    // per-stage copy mapping: 4 x 16B for A, 4 x 16B for B per thread
    int rowA[4], chA[4], nglB[4];
    #pragma unroll
    for (int i = 0; i < 4; ++i) {
        int cid = tid + i * 128;
        rowA[i] = cid & 127; chA[i] = cid >> 7;
        int rr = cid & 127;
        int tn = rr >> 3, win = rr & 7;
        nglB[i] = (tn & 3) * UNITS + j0 + (tn >> 2) * 8 + win;
    }

    auto load_stage = [&](int s, int buf) {
        const __nv_bfloat16* A; const __nv_bfloat16* B; int lda, k0;
        if (s < S1) { A = A1; B = B1; lda = K1;    k0 = s * BK; }
        else        { A = A2; B = B2; lda = UNITS; k0 = (s - S1) * BK; }
        __nv_bfloat16* As = smem + buf * SMEM_STAGE;
        __nv_bfloat16* Bs = As + BM * SSTR;
        #pragma unroll
        for (int i = 0; i < 4; ++i) {
            cpasync16(smem_u32(&As[rowA[i] * SSTR + chA[i] * 8]),
                      A + (size_t)(m0 + rowA[i]) * lda + k0 + chA[i] * 8);
            cpasync16(smem_u32(&Bs[rowA[i] * SSTR + chA[i] * 8]),
                      B + (size_t)nglB[i] * lda + k0 + chA[i] * 8);
        }
    };

    // accumulators initialized with bias (per-column, replicated over rows)
    const int jcbase = (lane & 3) * 2;           // col pair base within n8
    float acc[4][8][4];
    #pragma unroll
    for (int j = 0; j < 8; ++j) {
        int g = j & 3;
        int junit = j0 + (wn * 2 + (j >> 2)) * 8 + jcbase;
        float v0 = bias[g * UNITS + junit];
        float v1 = bias[g * UNITS + junit + 1];
        #pragma unroll
        for (int mt = 0; mt < 4; ++mt) {
            acc[mt][j][0] = v0; acc[mt][j][1] = v1;
            acc[mt][j][2] = v0; acc[mt][j][3] = v1;
        }
    }

    const int ar = wm * 64 + (lane >> 2);
    const int ac = (lane & 3) * 2;

    load_stage(0, 0); CP_COMMIT();
    load_stage(1, 1); CP_COMMIT();

    #pragma unroll 1
    for (int s = 0; s < S; ++s) {
        CP_WAIT(1);
        __syncthreads();                          // single barrier per stage
        if (s + 2 < S) load_stage(s + 2, (s + 2) & (NSTG - 1));
        CP_COMMIT();                              // uniform cadence (may be empty)

        const __nv_bfloat16* As = smem + (s & (NSTG - 1)) * SMEM_STAGE;
        const __nv_bfloat16* Bs = As + BM * SSTR;
        #pragma unroll
        for (int kk = 0; kk < BK; kk += 16) {
            uint32_t a[4][4], b[8][2];
            #pragma unroll
            for (int mt = 0; mt < 4; ++mt) {
                const __nv_bfloat16* p = &As[(ar + mt * 16) * SSTR + kk + ac];
                a[mt][0] = *(const uint32_t*)p;
                a[mt][1] = *(const uint32_t*)(p + 8 * SSTR);
                a[mt][2] = *(const uint32_t*)(p + 8);
                a[mt][3] = *(const uint32_t*)(p + 8 * SSTR + 8);
            }
            #pragma unroll
            for (int j = 0; j < 8; ++j) {
                const __nv_bfloat16* q = &Bs[((wn * 8 + j) * 8 + (lane >> 2)) * SSTR + kk + ac];
                b[j][0] = *(const uint32_t*)q;
                b[j][1] = *(const uint32_t*)(q + 8);
            }
            #pragma unroll
            for (int mt = 0; mt < 4; ++mt)
                #pragma unroll
                for (int j = 0; j < 8; ++j)
                    mma16816(acc[mt][j], a[mt], b[j]);
        }
        // no trailing barrier: NSTG=4 ring tolerates 1-stage warp skew
    }

    // ---- fused LSTM gate epilogue (Keras order: i, f, g, o) ----
    #pragma unroll
    for (int ub = 0; ub < 2; ++ub) {
        const int jc = j0 + (wn * 2 + ub) * 8 + jcbase;
        #pragma unroll
        for (int mt = 0; mt < 4; ++mt) {
            #pragma unroll
            for (int p = 0; p < 2; ++p) {
                const int brow = m0 + wm * 64 + mt * 16 + (lane >> 2) + p * 8;
                __nv_bfloat162 hv;
                #pragma unroll
                for (int q = 0; q < 2; ++q) {
                    float zi = acc[mt][ub * 4 + 0][p * 2 + q];
                    float zf = acc[mt][ub * 4 + 1][p * 2 + q];
                    float zg = acc[mt][ub * 4 + 2][p * 2 + q];
                    float zo = acc[mt][ub * 4 + 3][p * 2 + q];
                    size_t coff = (size_t)(jc + q) * BATCH + brow;
                    float cn = sigf(zf) * c_t[coff] + sigf(zi) * tanhf(zg);
                    c_t[coff] = cn;
                    ((__nv_bfloat16*)&hv)[q] = __float2bfloat16(sigf(zo) * tanhf(cn));
                }
                *(__nv_bfloat162*)(h_out + (size_t)brow * UNITS + jc) = hv;
            }
        }
    }
}

// ---------------------------------------------------------------------------
__global__ void fc_kernel(const float* __restrict__ fcW,
                          const float* __restrict__ fcb,
                          float* __restrict__ out) {
    const __nv_bfloat16* h1 = g_h1[T_LEN & 1];   // buffer written at t = T_LEN-1
    int b = blockIdx.x;
    int lane = threadIdx.x;            // 32
    float s = 0.f;
    for (int k = lane; k < UNITS; k += 32)
        s += __bfloat162float(h1[(size_t)b * UNITS + k]) * fcW[k];
    #pragma unroll
    for (int off = 16; off > 0; off >>= 1)
        s += __shfl_xor_sync(0xFFFFFFFFu, s, off);
    if (lane == 0) out[b] = sigf(s + fcb[0]);
}

// ---------------------------------------------------------------------------
extern "C" void kernel_launch(void* const* d_in, const int* in_sizes, int n_in,
                              void* d_out, int out_size) {
    const int*   inputs = (const int*)  d_in[0];
    const float* emb    = (const float*)d_in[1];
    const float* W0     = (const float*)d_in[2];
    const float* U0     = (const float*)d_in[3];
    const float* b0     = (const float*)d_in[4];
    const float* W1     = (const float*)d_in[5];
    const float* U1     = (const float*)d_in[6];
    const float* b1     = (const float*)d_in[7];
    const float* fcW    = (const float*)d_in[8];
    const float* fcb    = (const float*)d_in[9];
    float* out = (float*)d_out;

    cudaFuncSetAttribute(lstm_round, cudaFuncAttributeMaxDynamicSharedMemorySize, SMEM_BYTES);

    float *pc0, *pc1;
    cudaGetSymbolAddress((void**)&pc0, g_c0);
    cudaGetSymbolAddress((void**)&pc1, g_c1);

    // prologue: exactly 3 launches (keeps ncu -s 5 on the hot kernel)
    init_zero<<<512, 256>>>();
    transpose_all<<<dim3(NGATE / 32, 32, 4), dim3(32, 8)>>>(W0, U0, W1, U1);
    gather_x<<<T_LEN * BATCH, 128>>>(inputs, emb);

    dim3 grid(UNITS / BNU, BATCH / BM, 2);   // (32, 16, 2)
    for (int r = 0; r <= T_LEN; ++r)
        lstm_round<<<grid, 128, SMEM_BYTES>>>(b0, pc0, b1, pc1, r);

    fc_kernel<<<BATCH, 32>>>(fcW, fcb, out);
}

// round 6
// speedup vs baseline: 4.2213x; 1.0897x over previous
#include <cuda_runtime.h>
#include <cuda_bf16.h>
#include <math.h>
#include <cstdint>

#define T_LEN  80
#define BATCH  2048
#define EMB    100
#define EPAD   128
#define UNITS  1024
#define NGATE  4096

#define BM   128     // batch rows per CTA
#define BNU  32      // units per CTA (output cols = 4 gates * 32 = 128)
#define BK   32      // k per pipeline stage
#define NSTG 4       // cp.async pipeline depth (ring)
#define SSTR 40      // smem row stride in bf16 (conflict-free)

#define SMEM_STAGE  (2 * BM * SSTR)              // bf16 elems per stage (A+B)
#define STAGE_BYTES (SMEM_STAGE * 2)             // 20480
#define SMEM_BYTES  (NSTG * STAGE_BYTES)         // 81920 B

// ---- persistent scratch ----
__device__ __nv_bfloat16 g_X[(size_t)T_LEN*BATCH*EPAD];
__device__ __nv_bfloat16 g_W0t[(size_t)NGATE*EPAD];     // [4096][128]  K-major (transposed)
__device__ __nv_bfloat16 g_U0t[(size_t)NGATE*UNITS];    // [4096][1024]
__device__ __nv_bfloat16 g_W1t[(size_t)NGATE*UNITS];
__device__ __nv_bfloat16 g_U1t[(size_t)NGATE*UNITS];
__device__ __nv_bfloat16 g_h0s[(size_t)(T_LEN+1)*BATCH*UNITS];  // h0 ring, slot t
__device__ __nv_bfloat16 g_h1[2][(size_t)BATCH*UNITS];
__device__ float g_c0[(size_t)UNITS*BATCH];             // transposed [unit][batch]
__device__ float g_c1[(size_t)UNITS*BATCH];

__device__ __forceinline__ uint32_t smem_u32(const void* p) {
    uint32_t a;
    asm("{ .reg .u64 t; cvta.to.shared.u64 t, %1; cvt.u32.u64 %0, t; }" : "=r"(a) : "l"(p));
    return a;
}
__device__ __forceinline__ void cpasync16(uint32_t dst, const void* src) {
    asm volatile("cp.async.cg.shared.global [%0], [%1], 16;" :: "r"(dst), "l"(src));
}
#define CP_COMMIT() asm volatile("cp.async.commit_group;" ::: "memory")
#define CP_WAIT(n)  asm volatile("cp.async.wait_group %0;" :: "n"(n) : "memory")

#define LDSM_X4(r0,r1,r2,r3, addr) \
    asm volatile("ldmatrix.sync.aligned.m8n8.x4.shared.b16 {%0,%1,%2,%3}, [%4];" \
        : "=r"(r0), "=r"(r1), "=r"(r2), "=r"(r3) : "r"(addr))

__device__ __forceinline__ void mma16816(float* d, const uint32_t* a, const uint32_t* b) {
    asm volatile("mma.sync.aligned.m16n8k16.row.col.f32.bf16.bf16.f32 "
        "{%0,%1,%2,%3}, {%4,%5,%6,%7}, {%8,%9}, {%0,%1,%2,%3};"
        : "+f"(d[0]), "+f"(d[1]), "+f"(d[2]), "+f"(d[3])
        : "r"(a[0]), "r"(a[1]), "r"(a[2]), "r"(a[3]), "r"(b[0]), "r"(b[1]));
}

__device__ __forceinline__ float sigf(float x) { return 1.f / (1.f + expf(-x)); }

// ---------------------------------------------------------------------------
__global__ void init_zero() {
    uint32_t* h0 = (uint32_t*)g_h0s;            // slot 0
    uint32_t* h1 = (uint32_t*)g_h1[0];
    int stride = gridDim.x * blockDim.x;
    int i = blockIdx.x * blockDim.x + threadIdx.x;
    const int n16 = BATCH * UNITS / 2;
    for (int k = i; k < n16; k += stride) { h0[k] = 0u; h1[k] = 0u; }
    const int n32 = BATCH * UNITS;
    for (int k = i; k < n32; k += stride) { g_c0[k] = 0.f; g_c1[k] = 0.f; }
}

// transpose all 4 weight matrices fp32 [K][4096] -> bf16 [4096][Kpad]
__global__ void transpose_all(const float* __restrict__ W0, const float* __restrict__ U0,
                              const float* __restrict__ W1, const float* __restrict__ U1) {
    __shared__ float tile[32][33];
    const float* in; __nv_bfloat16* out; int K, Kpad;
    switch (blockIdx.z) {
        case 0:  in = W0; out = g_W0t; K = EMB;   Kpad = EPAD;  break;
        case 1:  in = U0; out = g_U0t; K = UNITS; Kpad = UNITS; break;
        case 2:  in = W1; out = g_W1t; K = UNITS; Kpad = UNITS; break;
        default: in = U1; out = g_U1t; K = UNITS; Kpad = UNITS; break;
    }
    int n0 = blockIdx.x * 32, k0 = blockIdx.y * 32;
    if (k0 >= Kpad) return;
    int tx = threadIdx.x, ty = threadIdx.y;   // 32 x 8
    for (int i = ty; i < 32; i += 8) {
        int k = k0 + i;
        tile[i][tx] = (k < K) ? in[(size_t)k * NGATE + n0 + tx] : 0.f;
    }
    __syncthreads();
    for (int i = ty; i < 32; i += 8) {
        int n = n0 + i, kk = k0 + tx;
        out[(size_t)n * Kpad + kk] = __float2bfloat16(tile[tx][i]);
    }
}

__global__ void gather_x(const int* __restrict__ inputs, const float* __restrict__ emb) {
    int blk = blockIdx.x;                 // t*BATCH + b
    int t = blk / BATCH, b = blk - t * BATCH;
    int e = threadIdx.x;                  // 128
    int idx = inputs[b * T_LEN + t];
    float v = (e < EMB) ? emb[(size_t)idx * EMB + e] : 0.f;
    g_X[(size_t)blk * EPAD + e] = __float2bfloat16(v);
}

// ---------------------------------------------------------------------------
// One "round": z==0 -> layer0 step r; z==1 -> layer1 step r-1 (independent).
// 256 threads, 8 warps, warp tile 32x64, ldmatrix fragment loads,
// 4-stage cp.async ring with one barrier per stage. N-tiles interleave gates
// (tn -> gate tn&3, unit-block tn>>2): each thread owns all 4 gates.
__global__ __launch_bounds__(256, 2)
void lstm_round(const float* __restrict__ b0, float* __restrict__ c0,
                const float* __restrict__ b1, float* __restrict__ c1,
                int r) {
    const __nv_bfloat16 *A1, *B1, *A2, *B2;
    const float* bias; float* c_t; __nv_bfloat16* h_out;
    int K1;
    if (blockIdx.z == 0) {
        if (r == T_LEN) return;
        A1 = g_X + (size_t)r * BATCH * EPAD;  K1 = EPAD;  B1 = g_W0t;
        A2 = g_h0s + (size_t)r * BATCH * UNITS;           B2 = g_U0t;
        bias = b0; c_t = c0;
        h_out = g_h0s + (size_t)(r + 1) * BATCH * UNITS;
    } else {
        if (r == 0) return;
        int t = r - 1;
        A1 = g_h0s + (size_t)(t + 1) * BATCH * UNITS;  K1 = UNITS;  B1 = g_W1t;
        A2 = g_h1[t & 1];                                            B2 = g_U1t;
        bias = b1; c_t = c1;
        h_out = g_h1[(t + 1) & 1];
    }

    extern __shared__ __align__(16) __nv_bfloat16 smem[];
    const int tid  = threadIdx.x;
    const int lane = tid & 31, wid = tid >> 5;
    const int wm = wid >> 1, wn = wid & 1;       // warp 32x64 at (wm, wn)
    const int m0 = blockIdx.y * BM, j0 = blockIdx.x * BNU;

    const int S1 = K1 / BK;
    const int S  = S1 + UNITS / BK;

    // cp.async mapping: per thread 2 A chunks + 2 B chunks (16B each)
    int rowA[2], chA[2], nglB[2];
    #pragma unroll
    for (int i = 0; i < 2; ++i) {
        int cid = tid + i * 256;
        rowA[i] = cid & 127; chA[i] = cid >> 7;   // ch 0..3
        int rr = cid & 127;
        int tn = rr >> 3, win = rr & 7;
        nglB[i] = (tn & 3) * UNITS + j0 + (tn >> 2) * 8 + win;
    }

    auto load_stage = [&](int s, int buf) {
        const __nv_bfloat16* A; const __nv_bfloat16* B; int lda, k0;
        if (s < S1) { A = A1; B = B1; lda = K1;    k0 = s * BK; }
        else        { A = A2; B = B2; lda = UNITS; k0 = (s - S1) * BK; }
        __nv_bfloat16* As = smem + buf * SMEM_STAGE;
        __nv_bfloat16* Bs = As + BM * SSTR;
        #pragma unroll
        for (int i = 0; i < 2; ++i) {
            cpasync16(smem_u32(&As[rowA[i] * SSTR + chA[i] * 8]),
                      A + (size_t)(m0 + rowA[i]) * lda + k0 + chA[i] * 8);
            cpasync16(smem_u32(&Bs[rowA[i] * SSTR + chA[i] * 8]),
                      B + (size_t)nglB[i] * lda + k0 + chA[i] * 8);
        }
    };

    // ldmatrix per-lane element offsets (in bf16 units)
    const int l7 = lane & 7, lg = lane >> 3;     // group 0..3
    int aoff[2], boff[4];
    #pragma unroll
    for (int mt = 0; mt < 2; ++mt) {
        int arow = wm * 32 + mt * 16 + ((lg & 1) << 3) + l7;
        aoff[mt] = arow * SSTR + ((lg >> 1) << 3);
    }
    #pragma unroll
    for (int jp = 0; jp < 4; ++jp) {
        int brow = (wn * 8 + jp * 2) * 8 + ((lg >> 1) << 3) + l7;
        boff[jp] = brow * SSTR + ((lg & 1) << 3);
    }

    // accumulators initialized with bias (per-column, replicated over rows)
    const int jcbase = (lane & 3) * 2;           // col pair base within n8
    float acc[2][8][4];
    #pragma unroll
    for (int j = 0; j < 8; ++j) {
        int g = j & 3;
        int junit = j0 + (wn * 2 + (j >> 2)) * 8 + jcbase;
        float v0 = bias[g * UNITS + junit];
        float v1 = bias[g * UNITS + junit + 1];
        #pragma unroll
        for (int mt = 0; mt < 2; ++mt) {
            acc[mt][j][0] = v0; acc[mt][j][1] = v1;
            acc[mt][j][2] = v0; acc[mt][j][3] = v1;
        }
    }

    const uint32_t smem_base = smem_u32(smem);

    load_stage(0, 0); CP_COMMIT();
    load_stage(1, 1); CP_COMMIT();

    #pragma unroll 1
    for (int s = 0; s < S; ++s) {
        CP_WAIT(1);
        __syncthreads();                          // single barrier per stage
        if (s + 2 < S) load_stage(s + 2, (s + 2) & (NSTG - 1));
        CP_COMMIT();                              // uniform cadence (may be empty)

        const uint32_t sA = smem_base + (s & (NSTG - 1)) * STAGE_BYTES;
        const uint32_t sB = sA + BM * SSTR * 2;
        #pragma unroll
        for (int kk = 0; kk < BK; kk += 16) {
            uint32_t a[2][4], b[8][2];
            #pragma unroll
            for (int mt = 0; mt < 2; ++mt)
                LDSM_X4(a[mt][0], a[mt][1], a[mt][2], a[mt][3],
                        sA + (aoff[mt] + kk) * 2);
            #pragma unroll
            for (int jp = 0; jp < 4; ++jp)
                LDSM_X4(b[jp * 2][0], b[jp * 2][1], b[jp * 2 + 1][0], b[jp * 2 + 1][1],
                        sB + (boff[jp] + kk) * 2);
            #pragma unroll
            for (int mt = 0; mt < 2; ++mt)
                #pragma unroll
                for (int j = 0; j < 8; ++j)
                    mma16816(acc[mt][j], a[mt], b[j]);
        }
        // no trailing barrier: NSTG=4 ring tolerates 1-stage warp skew
    }

    // ---- fused LSTM gate epilogue (Keras order: i, f, g, o) ----
    #pragma unroll
    for (int ub = 0; ub < 2; ++ub) {
        const int jc = j0 + (wn * 2 + ub) * 8 + jcbase;
        #pragma unroll
        for (int mt = 0; mt < 2; ++mt) {
            #pragma unroll
            for (int p = 0; p < 2; ++p) {
                const int brow = m0 + wm * 32 + mt * 16 + (lane >> 2) + p * 8;
                __nv_bfloat162 hv;
                #pragma unroll
                for (int q = 0; q < 2; ++q) {
                    float zi = acc[mt][ub * 4 + 0][p * 2 + q];
                    float zf = acc[mt][ub * 4 + 1][p * 2 + q];
                    float zg = acc[mt][ub * 4 + 2][p * 2 + q];
                    float zo = acc[mt][ub * 4 + 3][p * 2 + q];
                    size_t coff = (size_t)(jc + q) * BATCH + brow;
                    float cn = sigf(zf) * c_t[coff] + sigf(zi) * tanhf(zg);
                    c_t[coff] = cn;
                    ((__nv_bfloat16*)&hv)[q] = __float2bfloat16(sigf(zo) * tanhf(cn));
                }
                *(__nv_bfloat162*)(h_out + (size_t)brow * UNITS + jc) = hv;
            }
        }
    }
}

// ---------------------------------------------------------------------------
__global__ void fc_kernel(const float* __restrict__ fcW,
                          const float* __restrict__ fcb,
                          float* __restrict__ out) {
    const __nv_bfloat16* h1 = g_h1[T_LEN & 1];   // buffer written at t = T_LEN-1
    int b = blockIdx.x;
    int lane = threadIdx.x;            // 32
    float s = 0.f;
    for (int k = lane; k < UNITS; k += 32)
        s += __bfloat162float(h1[(size_t)b * UNITS + k]) * fcW[k];
    #pragma unroll
    for (int off = 16; off > 0; off >>= 1)
        s += __shfl_xor_sync(0xFFFFFFFFu, s, off);
    if (lane == 0) out[b] = sigf(s + fcb[0]);
}

// ---------------------------------------------------------------------------
extern "C" void kernel_launch(void* const* d_in, const int* in_sizes, int n_in,
                              void* d_out, int out_size) {
    const int*   inputs = (const int*)  d_in[0];
    const float* emb    = (const float*)d_in[1];
    const float* W0     = (const float*)d_in[2];
    const float* U0     = (const float*)d_in[3];
    const float* b0     = (const float*)d_in[4];
    const float* W1     = (const float*)d_in[5];
    const float* U1     = (const float*)d_in[6];
    const float* b1     = (const float*)d_in[7];
    const float* fcW    = (const float*)d_in[8];
    const float* fcb    = (const float*)d_in[9];
    float* out = (float*)d_out;

    cudaFuncSetAttribute(lstm_round, cudaFuncAttributeMaxDynamicSharedMemorySize, SMEM_BYTES);

    float *pc0, *pc1;
    cudaGetSymbolAddress((void**)&pc0, g_c0);
    cudaGetSymbolAddress((void**)&pc1, g_c1);

    // prologue: exactly 3 launches (keeps ncu -s 5 on the hot kernel)
    init_zero<<<512, 256>>>();
    transpose_all<<<dim3(NGATE / 32, 32, 4), dim3(32, 8)>>>(W0, U0, W1, U1);
    gather_x<<<T_LEN * BATCH, 128>>>(inputs, emb);

    dim3 grid(UNITS / BNU, BATCH / BM, 2);   // (32, 16, 2)
    for (int r = 0; r <= T_LEN; ++r)
        lstm_round<<<grid, 256, SMEM_BYTES>>>(b0, pc0, b1, pc1, r);

    fc_kernel<<<BATCH, 32>>>(fcW, fcb, out);
}

// round 7
// speedup vs baseline: 5.5181x; 1.3072x over previous
#include <cuda_runtime.h>
#include <cuda_bf16.h>
#include <cuda_fp8.h>
#include <math.h>
#include <cstdint>

#define T_LEN  80
#define BATCH  2048
#define EMB    100
#define UNITS  1024
#define NGATE  4096

// K dimensions in fp8-PAIR units (1 pair = 2 fp8 = 16 bits)
#define EPADP  64        // 128 fp8 (EMB=100 zero-padded)
#define UNITSP 512       // 1024 fp8

#define BM   128     // batch rows per CTA
#define BNU  32      // units per CTA (output cols = 4 gates * 32 = 128)
#define BK   32      // k PAIRS per pipeline stage (= 64 fp8)
#define NSTG 4       // cp.async pipeline depth (ring)
#define SSTR 40      // smem row stride in pairs (conflict-free)

#define SMEM_STAGE  (2 * BM * SSTR)              // pairs per stage (A+B)
#define STAGE_BYTES (SMEM_STAGE * 2)             // 20480
#define SMEM_BYTES  (NSTG * STAGE_BYTES)         // 81920 B

#define SCALE_A 256.0f   // activation (x, h) fp8 scale
#define SCALE_W 16.0f    // weight fp8 scale
#define INV_SCALE (1.0f / (SCALE_A * SCALE_W))

// ---- persistent scratch (all fp8 pairs stored as uint16) ----
__device__ uint16_t g_X[(size_t)T_LEN*BATCH*EPADP];
__device__ uint16_t g_W0t[(size_t)NGATE*EPADP];     // [4096][64p]  K-major (transposed)
__device__ uint16_t g_U0t[(size_t)NGATE*UNITSP];    // [4096][512p]
__device__ uint16_t g_W1t[(size_t)NGATE*UNITSP];
__device__ uint16_t g_U1t[(size_t)NGATE*UNITSP];
__device__ uint16_t g_h0s[(size_t)(T_LEN+1)*BATCH*UNITSP];  // h0 ring, slot t
__device__ uint16_t g_h1[2][(size_t)BATCH*UNITSP];
__device__ float g_c0[(size_t)UNITS*BATCH];             // transposed [unit][batch]
__device__ float g_c1[(size_t)UNITS*BATCH];

__device__ __forceinline__ uint32_t smem_u32(const void* p) {
    uint32_t a;
    asm("{ .reg .u64 t; cvta.to.shared.u64 t, %1; cvt.u32.u64 %0, t; }" : "=r"(a) : "l"(p));
    return a;
}
__device__ __forceinline__ void cpasync16(uint32_t dst, const void* src) {
    asm volatile("cp.async.cg.shared.global [%0], [%1], 16;" :: "r"(dst), "l"(src));
}
#define CP_COMMIT() asm volatile("cp.async.commit_group;" ::: "memory")
#define CP_WAIT(n)  asm volatile("cp.async.wait_group %0;" :: "n"(n) : "memory")

#define LDSM_X4(r0,r1,r2,r3, addr) \
    asm volatile("ldmatrix.sync.aligned.m8n8.x4.shared.b16 {%0,%1,%2,%3}, [%4];" \
        : "=r"(r0), "=r"(r1), "=r"(r2), "=r"(r3) : "r"(addr))

// fp8 e4m3 MMA: m16n8k32, fragment layout == m16n8k16.bf16 in pair units
__device__ __forceinline__ void mma16832(float* d, const uint32_t* a, const uint32_t* b) {
    asm volatile("mma.sync.aligned.m16n8k32.row.col.f32.e4m3.e4m3.f32 "
        "{%0,%1,%2,%3}, {%4,%5,%6,%7}, {%8,%9}, {%0,%1,%2,%3};"
        : "+f"(d[0]), "+f"(d[1]), "+f"(d[2]), "+f"(d[3])
        : "r"(a[0]), "r"(a[1]), "r"(a[2]), "r"(a[3]), "r"(b[0]), "r"(b[1]));
}

__device__ __forceinline__ float sigf(float x) { return 1.f / (1.f + expf(-x)); }

__device__ __forceinline__ uint16_t pack_fp8x2(float lo, float hi) {
    float2 v = make_float2(lo, hi);
    return (uint16_t)__nv_cvt_float2_to_fp8x2(v, __NV_SATFINITE, __NV_E4M3);
}

// ---------------------------------------------------------------------------
__global__ void init_zero() {
    uint32_t* h0 = (uint32_t*)g_h0s;            // slot 0
    uint32_t* h1 = (uint32_t*)g_h1[0];
    int stride = gridDim.x * blockDim.x;
    int i = blockIdx.x * blockDim.x + threadIdx.x;
    const int np = BATCH * UNITSP / 2;          // uint32 count
    for (int k = i; k < np; k += stride) { h0[k] = 0u; h1[k] = 0u; }
    const int n32 = BATCH * UNITS;
    for (int k = i; k < n32; k += stride) { g_c0[k] = 0.f; g_c1[k] = 0.f; }
}

// transpose fp32 [K][4096] -> fp8-pair [4096][Kp] with SCALE_W, zero-padded
__global__ void transpose_all(const float* __restrict__ W0, const float* __restrict__ U0,
                              const float* __restrict__ W1, const float* __restrict__ U1) {
    __shared__ float tile[64][33];
    const float* in; uint16_t* out; int K, Kp;
    switch (blockIdx.z) {
        case 0:  in = W0; out = g_W0t; K = EMB;   Kp = EPADP;  break;
        case 1:  in = U0; out = g_U0t; K = UNITS; Kp = UNITSP; break;
        case 2:  in = W1; out = g_W1t; K = UNITS; Kp = UNITSP; break;
        default: in = U1; out = g_U1t; K = UNITS; Kp = UNITSP; break;
    }
    int n0 = blockIdx.x * 32, kp0 = blockIdx.y * 32;    // 32 pairs = 64 k rows
    if (kp0 >= Kp) return;
    int tx = threadIdx.x, ty = threadIdx.y;   // 32 x 8
    for (int i = ty; i < 64; i += 8) {
        int k = kp0 * 2 + i;
        tile[i][tx] = (k < K) ? in[(size_t)k * NGATE + n0 + tx] * SCALE_W : 0.f;
    }
    __syncthreads();
    for (int i = ty; i < 32; i += 8) {
        int n = n0 + i;
        out[(size_t)n * Kp + kp0 + tx] = pack_fp8x2(tile[2 * tx][i], tile[2 * tx + 1][i]);
    }
}

// gather + pad embeddings -> fp8 pairs with SCALE_A
__global__ void gather_x(const int* __restrict__ inputs, const float* __restrict__ emb) {
    int blk = blockIdx.x;                 // t*BATCH + b
    int t = blk / BATCH, b = blk - t * BATCH;
    int e = threadIdx.x;                  // 64 (pair index)
    int idx = inputs[b * T_LEN + t];
    float v0 = (2 * e     < EMB) ? emb[(size_t)idx * EMB + 2 * e]     * SCALE_A : 0.f;
    float v1 = (2 * e + 1 < EMB) ? emb[(size_t)idx * EMB + 2 * e + 1] * SCALE_A : 0.f;
    g_X[(size_t)blk * EPADP + e] = pack_fp8x2(v0, v1);
}

// ---------------------------------------------------------------------------
// One "round": z==0 -> layer0 step r; z==1 -> layer1 step r-1 (independent).
// FP8 e4m3 GEMM (m16n8k32), all K addressing in PAIR units; 256 threads,
// 8 warps, warp tile 32x64, ldmatrix loads, 4-stage cp.async ring.
// N-tiles interleave gates so each thread owns all 4 gates of its coords.
__global__ __launch_bounds__(256, 2)
void lstm_round(const float* __restrict__ b0, float* __restrict__ c0,
                const float* __restrict__ b1, float* __restrict__ c1,
                int r) {
    const uint16_t *A1, *B1, *A2, *B2;
    const float* bias; float* c_t; uint16_t* h_out;
    int K1;   // pairs
    if (blockIdx.z == 0) {
        if (r == T_LEN) return;
        A1 = g_X + (size_t)r * BATCH * EPADP;  K1 = EPADP;  B1 = g_W0t;
        A2 = g_h0s + (size_t)r * BATCH * UNITSP;            B2 = g_U0t;
        bias = b0; c_t = c0;
        h_out = g_h0s + (size_t)(r + 1) * BATCH * UNITSP;
    } else {
        if (r == 0) return;
        int t = r - 1;
        A1 = g_h0s + (size_t)(t + 1) * BATCH * UNITSP;  K1 = UNITSP;  B1 = g_W1t;
        A2 = g_h1[t & 1];                                              B2 = g_U1t;
        bias = b1; c_t = c1;
        h_out = g_h1[(t + 1) & 1];
    }

    extern __shared__ __align__(16) uint16_t smem[];
    const int tid  = threadIdx.x;
    const int lane = tid & 31, wid = tid >> 5;
    const int wm = wid >> 1, wn = wid & 1;       // warp 32x64 at (wm, wn)
    const int m0 = blockIdx.y * BM, j0 = blockIdx.x * BNU;

    const int S1 = K1 / BK;
    const int S  = S1 + UNITSP / BK;

    // cp.async mapping: per thread 2 A chunks + 2 B chunks (16B = 8 pairs)
    int rowA[2], chA[2], nglB[2];
    #pragma unroll
    for (int i = 0; i < 2; ++i) {
        int cid = tid + i * 256;
        rowA[i] = cid & 127; chA[i] = cid >> 7;   // ch 0..3
        int rr = cid & 127;
        int tn = rr >> 3, win = rr & 7;
        nglB[i] = (tn & 3) * UNITS + j0 + (tn >> 2) * 8 + win;
    }

    auto load_stage = [&](int s, int buf) {
        const uint16_t* A; const uint16_t* B; int lda, k0;
        if (s < S1) { A = A1; B = B1; lda = K1;     k0 = s * BK; }
        else        { A = A2; B = B2; lda = UNITSP; k0 = (s - S1) * BK; }
        uint16_t* As = smem + buf * SMEM_STAGE;
        uint16_t* Bs = As + BM * SSTR;
        #pragma unroll
        for (int i = 0; i < 2; ++i) {
            cpasync16(smem_u32(&As[rowA[i] * SSTR + chA[i] * 8]),
                      A + (size_t)(m0 + rowA[i]) * lda + k0 + chA[i] * 8);
            cpasync16(smem_u32(&Bs[rowA[i] * SSTR + chA[i] * 8]),
                      B + (size_t)nglB[i] * lda + k0 + chA[i] * 8);
        }
    };

    // ldmatrix per-lane offsets (pair units)
    const int l7 = lane & 7, lg = lane >> 3;     // group 0..3
    int aoff[2], boff[4];
    #pragma unroll
    for (int mt = 0; mt < 2; ++mt) {
        int arow = wm * 32 + mt * 16 + ((lg & 1) << 3) + l7;
        aoff[mt] = arow * SSTR + ((lg >> 1) << 3);
    }
    #pragma unroll
    for (int jp = 0; jp < 4; ++jp) {
        int brow = (wn * 8 + jp * 2) * 8 + ((lg >> 1) << 3) + l7;
        boff[jp] = brow * SSTR + ((lg & 1) << 3);
    }

    float acc[2][8][4];
    #pragma unroll
    for (int j = 0; j < 8; ++j)
        #pragma unroll
        for (int mt = 0; mt < 2; ++mt) {
            acc[mt][j][0] = 0.f; acc[mt][j][1] = 0.f;
            acc[mt][j][2] = 0.f; acc[mt][j][3] = 0.f;
        }

    const uint32_t smem_base = smem_u32(smem);

    load_stage(0, 0); CP_COMMIT();
    load_stage(1, 1); CP_COMMIT();

    #pragma unroll 1
    for (int s = 0; s < S; ++s) {
        CP_WAIT(1);
        __syncthreads();                          // single barrier per stage
        if (s + 2 < S) load_stage(s + 2, (s + 2) & (NSTG - 1));
        CP_COMMIT();                              // uniform cadence (may be empty)

        const uint32_t sA = smem_base + (s & (NSTG - 1)) * STAGE_BYTES;
        const uint32_t sB = sA + BM * SSTR * 2;
        #pragma unroll
        for (int kk = 0; kk < BK; kk += 16) {     // two k32 mmas per stage
            uint32_t a[2][4], b[8][2];
            #pragma unroll
            for (int mt = 0; mt < 2; ++mt)
                LDSM_X4(a[mt][0], a[mt][1], a[mt][2], a[mt][3],
                        sA + (aoff[mt] + kk) * 2);
            #pragma unroll
            for (int jp = 0; jp < 4; ++jp)
                LDSM_X4(b[jp * 2][0], b[jp * 2][1], b[jp * 2 + 1][0], b[jp * 2 + 1][1],
                        sB + (boff[jp] + kk) * 2);
            #pragma unroll
            for (int mt = 0; mt < 2; ++mt)
                #pragma unroll
                for (int j = 0; j < 8; ++j)
                    mma16832(acc[mt][j], a[mt], b[j]);
        }
        // no trailing barrier: NSTG=4 ring tolerates 1-stage warp skew
    }

    // ---- fused LSTM gate epilogue (Keras order: i, f, g, o) ----
    const int jcbase = (lane & 3) * 2;           // even -> one fp8 pair
    #pragma unroll
    for (int ub = 0; ub < 2; ++ub) {
        const int jc = j0 + (wn * 2 + ub) * 8 + jcbase;
        float bi[2], bf[2], bg[2], bo[2];
        #pragma unroll
        for (int q = 0; q < 2; ++q) {
            bi[q] = bias[0 * UNITS + jc + q];
            bf[q] = bias[1 * UNITS + jc + q];
            bg[q] = bias[2 * UNITS + jc + q];
            bo[q] = bias[3 * UNITS + jc + q];
        }
        #pragma unroll
        for (int mt = 0; mt < 2; ++mt) {
            #pragma unroll
            for (int p = 0; p < 2; ++p) {
                const int brow = m0 + wm * 32 + mt * 16 + (lane >> 2) + p * 8;
                float hq[2];
                #pragma unroll
                for (int q = 0; q < 2; ++q) {
                    float zi = fmaf(acc[mt][ub * 4 + 0][p * 2 + q], INV_SCALE, bi[q]);
                    float zf = fmaf(acc[mt][ub * 4 + 1][p * 2 + q], INV_SCALE, bf[q]);
                    float zg = fmaf(acc[mt][ub * 4 + 2][p * 2 + q], INV_SCALE, bg[q]);
                    float zo = fmaf(acc[mt][ub * 4 + 3][p * 2 + q], INV_SCALE, bo[q]);
                    size_t coff = (size_t)(jc + q) * BATCH + brow;
                    float cn = sigf(zf) * c_t[coff] + sigf(zi) * tanhf(zg);
                    c_t[coff] = cn;
                    hq[q] = sigf(zo) * tanhf(cn) * SCALE_A;
                }
                h_out[(size_t)brow * UNITSP + (jc >> 1)] = pack_fp8x2(hq[0], hq[1]);
            }
        }
    }
}

// ---------------------------------------------------------------------------
__global__ void fc_kernel(const float* __restrict__ fcW,
                          const float* __restrict__ fcb,
                          float* __restrict__ out) {
    const uint8_t* h1 = (const uint8_t*)g_h1[T_LEN & 1];
    int b = blockIdx.x;
    int lane = threadIdx.x;            // 32
    float s = 0.f;
    for (int k = lane; k < UNITS; k += 32) {
        uint8_t byte = h1[(size_t)b * UNITS + k];
        float hv = (float)(*reinterpret_cast<const __nv_fp8_e4m3*>(&byte)) * (1.0f / SCALE_A);
        s += hv * fcW[k];
    }
    #pragma unroll
    for (int off = 16; off > 0; off >>= 1)
        s += __shfl_xor_sync(0xFFFFFFFFu, s, off);
    if (lane == 0) out[b] = sigf(s + fcb[0]);
}

// ---------------------------------------------------------------------------
extern "C" void kernel_launch(void* const* d_in, const int* in_sizes, int n_in,
                              void* d_out, int out_size) {
    const int*   inputs = (const int*)  d_in[0];
    const float* emb    = (const float*)d_in[1];
    const float* W0     = (const float*)d_in[2];
    const float* U0     = (const float*)d_in[3];
    const float* b0     = (const float*)d_in[4];
    const float* W1     = (const float*)d_in[5];
    const float* U1     = (const float*)d_in[6];
    const float* b1     = (const float*)d_in[7];
    const float* fcW    = (const float*)d_in[8];
    const float* fcb    = (const float*)d_in[9];
    float* out = (float*)d_out;

    cudaFuncSetAttribute(lstm_round, cudaFuncAttributeMaxDynamicSharedMemorySize, SMEM_BYTES);

    float *pc0, *pc1;
    cudaGetSymbolAddress((void**)&pc0, g_c0);
    cudaGetSymbolAddress((void**)&pc1, g_c1);

    // prologue: exactly 3 launches (keeps ncu -s 5 on the hot kernel)
    init_zero<<<512, 256>>>();
    transpose_all<<<dim3(NGATE / 32, UNITSP / 32, 4), dim3(32, 8)>>>(W0, U0, W1, U1);
    gather_x<<<T_LEN * BATCH, 64>>>(inputs, emb);

    dim3 grid(UNITS / BNU, BATCH / BM, 2);   // (32, 16, 2)
    for (int r = 0; r <= T_LEN; ++r)
        lstm_round<<<grid, 256, SMEM_BYTES>>>(b0, pc0, b1, pc1, r);

    fc_kernel<<<BATCH, 32>>>(fcW, fcb, out);
}